// round 1
// baseline (speedup 1.0000x reference)
#include <cuda_runtime.h>
#include <math.h>
#include <float.h>
#include <stdint.h>

// Problem constants
#define TOKENS_TOTAL (32*2048)   // 65536
#define IN_DIM   128
#define HID      64
#define OUT_DIM  64
#define CODEBOOK 2048

// Tiling
#define TB       128             // tokens per block
#define NTHREADS 256
#define CCHUNK   128             // codes per smem chunk
#define NCHUNK   (CODEBOOK/CCHUNK)   // 16
#define ES_STRIDE 68             // padded row stride (floats) for codebook chunk
#define XT_STRIDE 130            // padded row stride for transposed x tile

// Output layout: msg ++ idx(as float) ++ loss
#define MSG_ELEMS ((size_t)TOKENS_TOTAL*OUT_DIM)   // 4194304
#define IDX_OFF   MSG_ELEMS
#define LOSS_OFF  (MSG_ELEMS + TOKENS_TOTAL)       // 4259840

#define NBLOCKS (TOKENS_TOTAL/TB)                   // 512

// Shared memory regions (floats)
#define SA_SIZE 8448   // h1 [128][64], then x transposed [64][130]
#define SB_SIZE 8832   // weights [K][64]; then codebook chunk [128] stride 68 + e2[128]
#define SC_SIZE 8192   // obs half tile [64][128]; then h2 [128][64]; then reductions
#define SMEM_FLOATS (SA_SIZE + SB_SIZE + SC_SIZE)   // 25472 -> 101888 B

// Scratch (no allocation allowed -> device globals)
__device__ float g_e2[CODEBOOK];
__device__ float g_partial[NBLOCKS];

// ---------- packed fp32x2 helpers ----------
__device__ __forceinline__ unsigned long long dup2(float x) {
    unsigned long long r;
    asm("mov.b64 %0, {%1, %1};" : "=l"(r) : "f"(x));
    return r;
}
__device__ __forceinline__ void ffma2(unsigned long long& d,
                                      unsigned long long a,
                                      unsigned long long b) {
    asm("fma.rn.f32x2 %0, %1, %2, %0;" : "+l"(d) : "l"(a), "l"(b));
}
__device__ __forceinline__ float lo32(unsigned long long v) {
    return __uint_as_float((unsigned int)v);
}
__device__ __forceinline__ float hi32(unsigned long long v) {
    return __uint_as_float((unsigned int)(v >> 32));
}

// ---------- generic MLP layer on a token tile ----------
// in_s:  [tokens][KD] row-major (stride in_stride)
// w_s:   [KD][64] row-major in smem
// OUTMODE 0: out_s[t*64 + j] ; OUTMODE 1: out_s[j*XT_STRIDE + t] (transposed x)
template<int KD, int NT, int OUTMODE, bool RELU>
__device__ __forceinline__ void mlp_layer(const float* in_s, int in_stride,
                                          const float* w_s,
                                          const float* __restrict__ b_g,
                                          float* out_s, int tid)
{
    const int jg = tid & 7;     // 8 j-groups (each owns 8 output cols as 4 pairs)
    const int tg = tid >> 3;    // 32 token groups

    float bj[4][2];
#pragma unroll
    for (int jj = 0; jj < 4; jj++) {
        int j0 = jg*2 + 16*jj;
        bj[jj][0] = __ldg(b_g + j0);
        bj[jj][1] = __ldg(b_g + j0 + 1);
    }

    unsigned long long acc[NT][4];
#pragma unroll
    for (int it = 0; it < NT; it++)
#pragma unroll
        for (int jj = 0; jj < 4; jj++) acc[it][jj] = 0ULL;

#pragma unroll 4
    for (int k0 = 0; k0 < KD; k0 += 4) {
        float xin[NT][4];
#pragma unroll
        for (int it = 0; it < NT; it++) {
            float4 v = *(const float4*)(in_s + (tg*NT + it)*in_stride + k0);
            xin[it][0] = v.x; xin[it][1] = v.y; xin[it][2] = v.z; xin[it][3] = v.w;
        }
#pragma unroll
        for (int kk = 0; kk < 4; kk++) {
            unsigned long long wp[4];
#pragma unroll
            for (int jj = 0; jj < 4; jj++)
                wp[jj] = *(const unsigned long long*)(w_s + (k0+kk)*64 + jg*2 + 16*jj);
#pragma unroll
            for (int it = 0; it < NT; it++) {
                unsigned long long xd = dup2(xin[it][kk]);
#pragma unroll
                for (int jj = 0; jj < 4; jj++) ffma2(acc[it][jj], xd, wp[jj]);
            }
        }
    }

#pragma unroll
    for (int it = 0; it < NT; it++) {
        int t = tg*NT + it;
#pragma unroll
        for (int jj = 0; jj < 4; jj++) {
            int j0 = jg*2 + 16*jj;
            float v0 = lo32(acc[it][jj]) + bj[jj][0];
            float v1 = hi32(acc[it][jj]) + bj[jj][1];
            if (RELU) { v0 = fmaxf(v0, 0.0f); v1 = fmaxf(v1, 0.0f); }
            if (OUTMODE == 0) {
                out_s[t*64 + j0]     = v0;
                out_s[t*64 + j0 + 1] = v1;
            } else {
                out_s[j0*XT_STRIDE + t]       = v0;
                out_s[(j0 + 1)*XT_STRIDE + t] = v1;
            }
        }
    }
}

// ---------- codebook |e|^2 precompute ----------
__global__ void e2_kernel(const float* __restrict__ cb) {
    int c = blockIdx.x * blockDim.x + threadIdx.x;
    if (c < CODEBOOK) {
        const float4* r = (const float4*)(cb + (size_t)c * OUT_DIM);
        float s = 0.0f;
#pragma unroll
        for (int i = 0; i < OUT_DIM/4; i++) {
            float4 v = r[i];
            s += v.x*v.x + v.y*v.y + v.z*v.z + v.w*v.w;
        }
        g_e2[c] = s;
    }
}

// ---------- fused MLP + VQ kernel ----------
__global__ void __launch_bounds__(NTHREADS, 1)
vq_main(const float* __restrict__ obs,
        const float* __restrict__ W1, const float* __restrict__ b1,
        const float* __restrict__ W2, const float* __restrict__ b2,
        const float* __restrict__ W3, const float* __restrict__ b3,
        const float* __restrict__ cb,
        float* __restrict__ out)
{
    extern __shared__ float sm[];
    float* sA = sm;                          // 8448 floats
    float* sB = sm + SA_SIZE;                // 8832 floats
    float* sC = sm + SA_SIZE + SB_SIZE;      // 8192 floats
    float* sE = sB + CCHUNK * ES_STRIDE;     // e2 for current chunk (128 floats)

    const int tid  = threadIdx.x;
    const int tok0 = blockIdx.x * TB;

    // ================= MLP =================
    // layer 1: obs[128x128] @ W1[128x64] + b1, relu  (two halves of 64 tokens)
    {
        const float4* w4 = (const float4*)W1;
        float4* d4 = (float4*)sB;
        for (int i = tid; i < (IN_DIM*HID)/4; i += NTHREADS) d4[i] = w4[i];
    }
    for (int half = 0; half < 2; half++) {
        __syncthreads();
        {
            const float4* o4 = (const float4*)(obs + (size_t)(tok0 + half*64) * IN_DIM);
            float4* d4 = (float4*)sC;
            for (int i = tid; i < (64*IN_DIM)/4; i += NTHREADS) d4[i] = o4[i];
        }
        __syncthreads();
        mlp_layer<IN_DIM, 2, 0, true>(sC, IN_DIM, sB, b1, sA + half*64*HID, tid);
    }
    __syncthreads();
    // layer 2: h1[128x64] @ W2[64x64] + b2, relu -> sC
    {
        const float4* w4 = (const float4*)W2;
        float4* d4 = (float4*)sB;
        for (int i = tid; i < (HID*HID)/4; i += NTHREADS) d4[i] = w4[i];
    }
    __syncthreads();
    mlp_layer<HID, 4, 0, true>(sA, HID, sB, b2, sC, tid);
    __syncthreads();
    // layer 3: h2[128x64] @ W3[64x64] + b3 -> x, stored TRANSPOSED in sA [64][130]
    {
        const float4* w4 = (const float4*)W3;
        float4* d4 = (float4*)sB;
        for (int i = tid; i < (HID*OUT_DIM)/4; i += NTHREADS) d4[i] = w4[i];
    }
    __syncthreads();
    mlp_layer<HID, 4, 1, false>(sC, HID, sB, b3, sA, tid);

    // ================= VQ =================
    const int cg = tid & 15;     // 16 code groups (8 codes each, interleaved c = cg + 16*i)
    const int tg = tid >> 4;     // 16 token groups (8 tokens each as 4 pairs)
    const float* xsT = sA;

    float best_d[8];
    int   best_c[8];
#pragma unroll
    for (int u = 0; u < 8; u++) { best_d[u] = FLT_MAX; best_c[u] = 0; }

    for (int ch = 0; ch < NCHUNK; ch++) {
        const int cb0 = ch * CCHUNK;
        __syncthreads();   // previous chunk consumers done (and first iter: W3/sB free)
        {
            const float4* c4 = (const float4*)(cb + (size_t)cb0 * OUT_DIM);
            for (int i = tid; i < (CCHUNK*OUT_DIM)/4; i += NTHREADS) {
                int c  = i >> 4;      // code within chunk
                int kq = i & 15;      // k quad
                *(float4*)(sB + c*ES_STRIDE + kq*4) = c4[i];
            }
            if (tid < CCHUNK) sE[tid] = g_e2[cb0 + tid];
        }
        __syncthreads();

        float e2r[8];
#pragma unroll
        for (int i = 0; i < 8; i++) e2r[i] = sE[cg + 16*i];

        unsigned long long acc[8][4];
#pragma unroll
        for (int i = 0; i < 8; i++)
#pragma unroll
            for (int jj = 0; jj < 4; jj++) acc[i][jj] = 0ULL;

#pragma unroll 4
        for (int k0 = 0; k0 < OUT_DIM; k0 += 4) {
            float evf[8][4];
#pragma unroll
            for (int i = 0; i < 8; i++) {
                float4 v = *(const float4*)(sB + (cg + 16*i)*ES_STRIDE + k0);
                evf[i][0] = v.x; evf[i][1] = v.y; evf[i][2] = v.z; evf[i][3] = v.w;
            }
#pragma unroll
            for (int kk = 0; kk < 4; kk++) {
                unsigned long long xp[4];
#pragma unroll
                for (int jj = 0; jj < 4; jj++)
                    xp[jj] = *(const unsigned long long*)
                             (xsT + (k0+kk)*XT_STRIDE + tg*2 + 32*jj);
#pragma unroll
                for (int i = 0; i < 8; i++) {
                    unsigned long long ed = dup2(evf[i][kk]);
#pragma unroll
                    for (int jj = 0; jj < 4; jj++) ffma2(acc[i][jj], ed, xp[jj]);
                }
            }
        }

        // per-chunk argmin update: d = e2 - 2*s  (x^2 is token-constant, argmin-equivalent)
#pragma unroll
        for (int i = 0; i < 8; i++) {
            const int   c   = cb0 + cg + 16*i;   // ascending within thread
            const float e2v = e2r[i];
#pragma unroll
            for (int jj = 0; jj < 4; jj++) {
                float d0 = fmaf(-2.0f, lo32(acc[i][jj]), e2v);
                float d1 = fmaf(-2.0f, hi32(acc[i][jj]), e2v);
                int u0 = jj*2, u1 = jj*2 + 1;
                if (d0 < best_d[u0]) { best_d[u0] = d0; best_c[u0] = c; }
                if (d1 < best_d[u1]) { best_d[u1] = d1; best_c[u1] = c; }
            }
        }
    }

    // ---- cross-thread argmin reduction (16 cg threads per token) ----
    float2* sRed = (float2*)sC;   // [128 tokens][16 groups]
#pragma unroll
    for (int u = 0; u < 8; u++) {
        int t = tg*2 + 32*(u >> 1) + (u & 1);
        sRed[t*16 + cg] = make_float2(best_d[u], __int_as_float(best_c[u]));
    }
    __syncthreads();

    int* sIdx = (int*)sE;   // 128 ints (e2 region no longer needed)
    if (tid < TB) {
        int t = tid;
        float bd = FLT_MAX;
        int   bc = 0x7fffffff;
#pragma unroll
        for (int g = 0; g < 16; g++) {
            float2 v = sRed[t*16 + g];
            int c = __float_as_int(v.y);
            if (v.x < bd || (v.x == bd && c < bc)) { bd = v.x; bc = c; }
        }
        sIdx[t] = bc;
        out[IDX_OFF + (size_t)(tok0 + t)] = (float)bc;
    }
    __syncthreads();

    // ---- msg write + commitment-loss partial ----
    float part = 0.0f;
    for (int f = tid; f < TB*OUT_DIM; f += NTHREADS) {
        int t = f >> 6, j = f & 63;
        int c = sIdx[t];
        float q  = __ldg(cb + (size_t)c * OUT_DIM + j);
        float xv = xsT[j*XT_STRIDE + t];
        out[(size_t)(tok0 + t)*OUT_DIM + j] = xv + (q - xv);  // straight-through, matches ref
        float dd = q - xv;
        part += dd * dd;
    }
#pragma unroll
    for (int o = 16; o > 0; o >>= 1)
        part += __shfl_down_sync(0xffffffffu, part, o);
    __shared__ float swred[8];
    if ((tid & 31) == 0) swred[tid >> 5] = part;
    __syncthreads();
    if (tid == 0) {
        float s = 0.0f;
#pragma unroll
        for (int w = 0; w < 8; w++) s += swred[w];
        g_partial[blockIdx.x] = s;
    }
}

// ---------- deterministic loss reduction ----------
__global__ void loss_reduce(float* __restrict__ out) {
    __shared__ float s[NBLOCKS];
    int t = threadIdx.x;
    s[t] = g_partial[t];
    __syncthreads();
    for (int o = NBLOCKS/2; o > 0; o >>= 1) {
        if (t < o) s[t] += s[t + o];
        __syncthreads();
    }
    if (t == 0) out[LOSS_OFF] = s[0] * (1.0f / (float)MSG_ELEMS);
}

extern "C" void kernel_launch(void* const* d_in, const int* in_sizes, int n_in,
                              void* d_out, int out_size)
{
    const float* obs = (const float*)d_in[0];
    const float* W1  = (const float*)d_in[1];
    const float* b1  = (const float*)d_in[2];
    const float* W2  = (const float*)d_in[3];
    const float* b2  = (const float*)d_in[4];
    const float* W3  = (const float*)d_in[5];
    const float* b3  = (const float*)d_in[6];
    const float* cb  = (const float*)d_in[7];
    float* out = (float*)d_out;

    cudaFuncSetAttribute(vq_main, cudaFuncAttributeMaxDynamicSharedMemorySize,
                         SMEM_FLOATS * (int)sizeof(float));

    e2_kernel<<<CODEBOOK/256, 256>>>(cb);
    vq_main<<<NBLOCKS, NTHREADS, SMEM_FLOATS * sizeof(float)>>>(
        obs, W1, b1, W2, b2, W3, b3, cb, out);
    loss_reduce<<<1, NBLOCKS>>>(out);
}

// round 3
// speedup vs baseline: 1.1895x; 1.1895x over previous
#include <cuda_runtime.h>
#include <math.h>
#include <float.h>
#include <stdint.h>

// ---------------- problem constants ----------------
#define TOKENS_TOTAL (32*2048)
#define IN_DIM   128
#define HID      64
#define OUT_DIM  64
#define CODEBOOK 2048

#define TB       128
#define NTHREADS 256
#define NBLOCKS  (TOKENS_TOTAL/TB)     // 512
#define XT_STRIDE 130
#define CCH      64                     // codes per staged chunk
#define NCH      (CODEBOOK/CCH)         // 32

// output layout: msg ++ idx(as float) ++ loss
#define MSG_ELEMS ((size_t)TOKENS_TOTAL*OUT_DIM)
#define IDX_OFF   MSG_ELEMS
#define LOSS_OFF  (MSG_ELEMS + TOKENS_TOTAL)

// ---------------- smem layout (float offsets) ----------------
#define OFF_E2   0                      // 2048 f
#define OFF_XT   2048                   // 64 x 130 f = 8320
#define OFF_B    10368                  // 2 bufs x (hi 64x68 + lo 64x68) = 2*8704 = 17408
#define B_BUF_STRIDE 8704
#define B_LO_OFF     4352
#define SMEM_FLOATS  27776              // 111104 bytes

// MLP-phase overlays (regions dead during MLP)
#define OFF_W    10368                  // weights (<= 8192 f), inside B region
#define OFF_OBS  18560                  // obs tile / h2 (8192 f), inside B region
#define OFF_H1   2048                   // h1 (8192 f), overlays XT (written later)

__device__ float g_e2[CODEBOOK];
__device__ float g_partial[NBLOCKS];

// ---------------- tf32 helpers ----------------
__device__ __forceinline__ uint32_t f2tf32(float x) {
    uint32_t u;
    asm("cvt.rna.tf32.f32 %0, %1;" : "=r"(u) : "f"(x));
    return u;
}
__device__ __forceinline__ void split_tf32(float x, uint32_t& h, float& l) {
    h = f2tf32(x);
    l = x - __uint_as_float(h);   // exact; residual fed to mma as raw fp32 (truncated ~2^-24 class)
}

__device__ __forceinline__ void mma8(float* c, const uint32_t* a, uint32_t b0, uint32_t b1) {
    asm volatile(
        "mma.sync.aligned.m16n8k8.row.col.f32.tf32.tf32.f32 "
        "{%0,%1,%2,%3}, {%4,%5,%6,%7}, {%8,%9}, {%0,%1,%2,%3};"
        : "+f"(c[0]), "+f"(c[1]), "+f"(c[2]), "+f"(c[3])
        : "r"(a[0]), "r"(a[1]), "r"(a[2]), "r"(a[3]), "r"(b0), "r"(b1));
}

// ---------------- packed fp32x2 helpers (MLP) ----------------
__device__ __forceinline__ unsigned long long dup2(float x) {
    unsigned long long r; asm("mov.b64 %0, {%1, %1};" : "=l"(r) : "f"(x)); return r;
}
__device__ __forceinline__ void ffma2(unsigned long long& d, unsigned long long a, unsigned long long b) {
    asm("fma.rn.f32x2 %0, %1, %2, %0;" : "+l"(d) : "l"(a), "l"(b));
}
__device__ __forceinline__ float lo32(unsigned long long v) { return __uint_as_float((unsigned)v); }
__device__ __forceinline__ float hi32(unsigned long long v) { return __uint_as_float((unsigned)(v >> 32)); }

// ---------------- MLP layer (proven in round 1) ----------------
template<int KD, int NT, int OUTMODE, bool RELU>
__device__ __forceinline__ void mlp_layer(const float* in_s, int in_stride,
                                          const float* w_s, const float* __restrict__ b_g,
                                          float* out_s, int tid)
{
    const int jg = tid & 7;
    const int tg = tid >> 3;
    float bj[4][2];
#pragma unroll
    for (int jj = 0; jj < 4; jj++) {
        int j0 = jg*2 + 16*jj;
        bj[jj][0] = __ldg(b_g + j0);
        bj[jj][1] = __ldg(b_g + j0 + 1);
    }
    unsigned long long acc[NT][4];
#pragma unroll
    for (int it = 0; it < NT; it++)
#pragma unroll
        for (int jj = 0; jj < 4; jj++) acc[it][jj] = 0ULL;

#pragma unroll 4
    for (int k0 = 0; k0 < KD; k0 += 4) {
        float xin[NT][4];
#pragma unroll
        for (int it = 0; it < NT; it++) {
            float4 v = *(const float4*)(in_s + (tg*NT + it)*in_stride + k0);
            xin[it][0] = v.x; xin[it][1] = v.y; xin[it][2] = v.z; xin[it][3] = v.w;
        }
#pragma unroll
        for (int kk = 0; kk < 4; kk++) {
            unsigned long long wp[4];
#pragma unroll
            for (int jj = 0; jj < 4; jj++)
                wp[jj] = *(const unsigned long long*)(w_s + (k0+kk)*64 + jg*2 + 16*jj);
#pragma unroll
            for (int it = 0; it < NT; it++) {
                unsigned long long xd = dup2(xin[it][kk]);
#pragma unroll
                for (int jj = 0; jj < 4; jj++) ffma2(acc[it][jj], xd, wp[jj]);
            }
        }
    }
#pragma unroll
    for (int it = 0; it < NT; it++) {
        int t = tg*NT + it;
#pragma unroll
        for (int jj = 0; jj < 4; jj++) {
            int j0 = jg*2 + 16*jj;
            float v0 = lo32(acc[it][jj]) + bj[jj][0];
            float v1 = hi32(acc[it][jj]) + bj[jj][1];
            if (RELU) { v0 = fmaxf(v0, 0.0f); v1 = fmaxf(v1, 0.0f); }
            if (OUTMODE == 0) {
                out_s[t*64 + j0]     = v0;
                out_s[t*64 + j0 + 1] = v1;
            } else {
                out_s[j0*XT_STRIDE + t]       = v0;
                out_s[(j0 + 1)*XT_STRIDE + t] = v1;
            }
        }
    }
}

// ---------------- |e|^2 precompute ----------------
__global__ void e2_kernel(const float* __restrict__ cb) {
    int c = blockIdx.x * blockDim.x + threadIdx.x;
    if (c < CODEBOOK) {
        const float4* r = (const float4*)(cb + (size_t)c * OUT_DIM);
        float s = 0.0f;
#pragma unroll
        for (int i = 0; i < OUT_DIM/4; i++) {
            float4 v = r[i];
            s += v.x*v.x + v.y*v.y + v.z*v.z + v.w*v.w;
        }
        g_e2[c] = s;
    }
}

// ---------------- codebook chunk staging ----------------
__device__ __forceinline__ void b_ldg(const float* __restrict__ cb, int ch, int tid, float4* v) {
    int c = tid >> 2, qg = tid & 3;   // code 0..63, quad-group 0..3
    const float4* p = (const float4*)(cb + (size_t)(ch*CCH + c)*OUT_DIM + qg*16);
#pragma unroll
    for (int i = 0; i < 4; i++) v[i] = p[i];
}
__device__ __forceinline__ void b_sts(float* bh, int tid, const float4* v) {
    int c = tid >> 2, qg = tid & 3;
    float* bl = bh + B_LO_OFF;
#pragma unroll
    for (int i = 0; i < 4; i++) {
        int q = qg*4 + i;                 // float4 index within row (16 per row)
        uint32_t h0, h1, h2, h3; float l0, l1, l2, l3;
        split_tf32(v[i].x, h0, l0);
        split_tf32(v[i].y, h1, l1);
        split_tf32(v[i].z, h2, l2);
        split_tf32(v[i].w, h3, l3);
        int off = c*68 + q*4;
        float4 hv = make_float4(__uint_as_float(h0), __uint_as_float(h1),
                                __uint_as_float(h2), __uint_as_float(h3));
        *(float4*)(bh + off) = hv;
        *(float4*)(bl + off) = make_float4(l0, l1, l2, l3);
    }
}

// ---------------- fused kernel ----------------
__global__ void __launch_bounds__(NTHREADS, 1)
vq_main(const float* __restrict__ obs,
        const float* __restrict__ W1, const float* __restrict__ b1,
        const float* __restrict__ W2, const float* __restrict__ b2,
        const float* __restrict__ W3, const float* __restrict__ b3,
        const float* __restrict__ cb,
        float* __restrict__ out)
{
    extern __shared__ float sm[];
    const int tid  = threadIdx.x;
    const int wid  = tid >> 5;
    const int lane = tid & 31;
    const int r    = lane >> 2;      // 0..7
    const int q    = lane & 3;       // 0..3
    const int tok0 = blockIdx.x * TB;

    // e2 table -> smem (region unused by MLP)
    for (int i = tid; i < CODEBOOK; i += NTHREADS) sm[OFF_E2 + i] = g_e2[i];

    // ================= MLP (FFMA2) =================
    {
        const float4* w4 = (const float4*)W1;
        float4* d4 = (float4*)(sm + OFF_W);
        for (int i = tid; i < (IN_DIM*HID)/4; i += NTHREADS) d4[i] = w4[i];
    }
    for (int half = 0; half < 2; half++) {
        __syncthreads();
        const float4* o4 = (const float4*)(obs + (size_t)(tok0 + half*64) * IN_DIM);
        float4* d4 = (float4*)(sm + OFF_OBS);
        for (int i = tid; i < (64*IN_DIM)/4; i += NTHREADS) d4[i] = o4[i];
        __syncthreads();
        mlp_layer<IN_DIM, 2, 0, true>(sm + OFF_OBS, IN_DIM, sm + OFF_W, b1,
                                      sm + OFF_H1 + half*64*HID, tid);
    }
    __syncthreads();
    {
        const float4* w4 = (const float4*)W2;
        float4* d4 = (float4*)(sm + OFF_W);
        for (int i = tid; i < (HID*HID)/4; i += NTHREADS) d4[i] = w4[i];
    }
    __syncthreads();
    mlp_layer<HID, 4, 0, true>(sm + OFF_H1, HID, sm + OFF_W, b2, sm + OFF_OBS, tid);
    __syncthreads();
    {
        const float4* w4 = (const float4*)W3;
        float4* d4 = (float4*)(sm + OFF_W);
        for (int i = tid; i < (HID*OUT_DIM)/4; i += NTHREADS) d4[i] = w4[i];
    }
    __syncthreads();
    // x -> XT [64 k][130 tokens], exact fp32 (overlays dead h1)
    mlp_layer<HID, 4, 1, false>(sm + OFF_OBS, HID, sm + OFF_W, b3, sm + OFF_XT, tid);
    __syncthreads();

    // ========== A fragments (m16 x k64, hi/lo), built once per warp ==========
    // a(row,k) = XT[k*130 + tok0w + row]; fragment layout per PTX m16n8k8 tf32.
    const float* xsT = sm + OFF_XT;
    const int tokw = wid * 16;
    uint32_t Ah[8][4], Al[8][4];
#pragma unroll
    for (int kb = 0; kb < 8; kb++) {
        int k0 = kb*8;
        float a0 = xsT[(k0 + q    )*XT_STRIDE + tokw + r    ];
        float a1 = xsT[(k0 + q    )*XT_STRIDE + tokw + r + 8];
        float a2 = xsT[(k0 + q + 4)*XT_STRIDE + tokw + r    ];
        float a3 = xsT[(k0 + q + 4)*XT_STRIDE + tokw + r + 8];
        float l;
        split_tf32(a0, Ah[kb][0], l); Al[kb][0] = __float_as_uint(l);
        split_tf32(a1, Ah[kb][1], l); Al[kb][1] = __float_as_uint(l);
        split_tf32(a2, Ah[kb][2], l); Al[kb][2] = __float_as_uint(l);
        split_tf32(a3, Ah[kb][3], l); Al[kb][3] = __float_as_uint(l);
    }

    // ================= VQ: mma.sync tf32, 3-term split =================
    float best_d0 = FLT_MAX, best_d1 = FLT_MAX;
    int   best_c0 = 0,       best_c1 = 0;

    // prologue: stage chunk 0 into buf 0
    {
        float4 st[4];
        b_ldg(cb, 0, tid, st);
        b_sts(sm + OFF_B, tid, st);
        __syncthreads();
    }

    for (int ch = 0; ch < NCH; ch++) {
        const int buf = ch & 1;
        float4 st[4];
        const bool more = (ch + 1 < NCH);
        if (more) b_ldg(cb, ch + 1, tid, st);   // prefetch next chunk (L2-latency hidden)

        const uint32_t* bh = (const uint32_t*)(sm + OFF_B + buf*B_BUF_STRIDE);
        const uint32_t* bl = bh + B_LO_OFF;

#pragma unroll
        for (int grp = 0; grp < 2; grp++) {
            float accM[4][4], accC1[4][4], accC2[4][4];
#pragma unroll
            for (int g = 0; g < 4; g++)
#pragma unroll
                for (int j = 0; j < 4; j++) { accM[g][j] = 0.f; accC1[g][j] = 0.f; accC2[g][j] = 0.f; }

            // per-g B row base: code_local = grp*32 + g*8 + r
            int rb0 = (grp*32 +  0 + r)*68 + q;
            int rb1 = (grp*32 +  8 + r)*68 + q;
            int rb2 = (grp*32 + 16 + r)*68 + q;
            int rb3 = (grp*32 + 24 + r)*68 + q;

#pragma unroll
            for (int kb = 0; kb < 8; kb++) {
                int ko = kb*8;
                uint32_t bh0[4], bh1[4], bl0[4], bl1[4];
                bh0[0] = bh[rb0 + ko]; bh1[0] = bh[rb0 + ko + 4];
                bh0[1] = bh[rb1 + ko]; bh1[1] = bh[rb1 + ko + 4];
                bh0[2] = bh[rb2 + ko]; bh1[2] = bh[rb2 + ko + 4];
                bh0[3] = bh[rb3 + ko]; bh1[3] = bh[rb3 + ko + 4];
                bl0[0] = bl[rb0 + ko]; bl1[0] = bl[rb0 + ko + 4];
                bl0[1] = bl[rb1 + ko]; bl1[1] = bl[rb1 + ko + 4];
                bl0[2] = bl[rb2 + ko]; bl1[2] = bl[rb2 + ko + 4];
                bl0[3] = bl[rb3 + ko]; bl1[3] = bl[rb3 + ko + 4];
#pragma unroll
                for (int g = 0; g < 4; g++) mma8(accM[g],  Ah[kb], bh0[g], bh1[g]);
#pragma unroll
                for (int g = 0; g < 4; g++) mma8(accC1[g], Ah[kb], bl0[g], bl1[g]);
#pragma unroll
                for (int g = 0; g < 4; g++) mma8(accC2[g], Al[kb], bh0[g], bh1[g]);
            }

            // epilogue: dist = e2 - 2*s, running argmin (codes ascending)
#pragma unroll
            for (int g = 0; g < 4; g++) {
                int code0 = ch*CCH + grp*32 + g*8 + 2*q;
                float e20 = sm[OFF_E2 + code0];
                float e21 = sm[OFF_E2 + code0 + 1];
                float s0 = accM[g][0] + accC1[g][0] + accC2[g][0];
                float s1 = accM[g][1] + accC1[g][1] + accC2[g][1];
                float s2 = accM[g][2] + accC1[g][2] + accC2[g][2];
                float s3 = accM[g][3] + accC1[g][3] + accC2[g][3];
                float d0 = fmaf(-2.0f, s0, e20);
                float d1 = fmaf(-2.0f, s1, e21);
                float d2 = fmaf(-2.0f, s2, e20);
                float d3 = fmaf(-2.0f, s3, e21);
                if (d0 < best_d0) { best_d0 = d0; best_c0 = code0; }
                if (d1 < best_d0) { best_d0 = d1; best_c0 = code0 + 1; }
                if (d2 < best_d1) { best_d1 = d2; best_c1 = code0; }
                if (d3 < best_d1) { best_d1 = d3; best_c1 = code0 + 1; }
            }
        }

        __syncthreads();                 // all warps done reading buf^1 from prior iter
        if (more) b_sts(sm + OFF_B + (1 - buf)*B_BUF_STRIDE, tid, st);
        __syncthreads();                 // staged data visible before next compute
    }

    // ---- cross-lane argmin (4 lanes per token row), tie-break: smaller code ----
#pragma unroll
    for (int m = 1; m <= 2; m <<= 1) {
        float od0 = __shfl_xor_sync(0xffffffffu, best_d0, m);
        int   oc0 = __shfl_xor_sync(0xffffffffu, best_c0, m);
        float od1 = __shfl_xor_sync(0xffffffffu, best_d1, m);
        int   oc1 = __shfl_xor_sync(0xffffffffu, best_c1, m);
        if (od0 < best_d0 || (od0 == best_d0 && oc0 < best_c0)) { best_d0 = od0; best_c0 = oc0; }
        if (od1 < best_d1 || (od1 == best_d1 && oc1 < best_c1)) { best_d1 = od1; best_c1 = oc1; }
    }

    int* sIdx = (int*)(sm + OFF_B);      // B region dead now
    if (q == 0) {
        int t0 = tokw + r;
        sIdx[t0]     = best_c0;
        sIdx[t0 + 8] = best_c1;
        out[IDX_OFF + (size_t)(tok0 + t0)]     = (float)best_c0;
        out[IDX_OFF + (size_t)(tok0 + t0 + 8)] = (float)best_c1;
    }
    __syncthreads();

    // ---- msg write + commitment-loss partial (exact fp32 x) ----
    float part = 0.0f;
    for (int f = tid; f < TB*OUT_DIM; f += NTHREADS) {
        int t = f >> 6, j = f & 63;
        int c = sIdx[t];
        float qv = __ldg(cb + (size_t)c * OUT_DIM + j);
        float xv = xsT[j*XT_STRIDE + t];
        out[(size_t)(tok0 + t)*OUT_DIM + j] = xv + (qv - xv);
        float dd = qv - xv;
        part += dd * dd;
    }
#pragma unroll
    for (int o = 16; o > 0; o >>= 1)
        part += __shfl_down_sync(0xffffffffu, part, o);
    __shared__ float swred[8];
    if ((tid & 31) == 0) swred[tid >> 5] = part;
    __syncthreads();
    if (tid == 0) {
        float s = 0.0f;
#pragma unroll
        for (int w = 0; w < 8; w++) s += swred[w];
        g_partial[blockIdx.x] = s;
    }
}

// ---------------- deterministic loss reduction ----------------
__global__ void loss_reduce(float* __restrict__ out) {
    __shared__ float s[NBLOCKS];
    int t = threadIdx.x;
    s[t] = g_partial[t];
    __syncthreads();
    for (int o = NBLOCKS/2; o > 0; o >>= 1) {
        if (t < o) s[t] += s[t + o];
        __syncthreads();
    }
    if (t == 0) out[LOSS_OFF] = s[0] * (1.0f / (float)MSG_ELEMS);
}

extern "C" void kernel_launch(void* const* d_in, const int* in_sizes, int n_in,
                              void* d_out, int out_size)
{
    const float* obs = (const float*)d_in[0];
    const float* W1  = (const float*)d_in[1];
    const float* b1  = (const float*)d_in[2];
    const float* W2  = (const float*)d_in[3];
    const float* b2  = (const float*)d_in[4];
    const float* W3  = (const float*)d_in[5];
    const float* b3  = (const float*)d_in[6];
    const float* cb  = (const float*)d_in[7];
    float* out = (float*)d_out;

    cudaFuncSetAttribute(vq_main, cudaFuncAttributeMaxDynamicSharedMemorySize,
                         SMEM_FLOATS * (int)sizeof(float));

    e2_kernel<<<CODEBOOK/256, 256>>>(cb);
    vq_main<<<NBLOCKS, NTHREADS, SMEM_FLOATS * sizeof(float)>>>(
        obs, W1, b1, W2, b2, W3, b3, cb, out);
    loss_reduce<<<1, NBLOCKS>>>(out);
}

// round 4
// speedup vs baseline: 1.7900x; 1.5048x over previous
#include <cuda_runtime.h>
#include <cuda_fp16.h>
#include <math.h>
#include <float.h>
#include <stdint.h>

// ---------------- problem constants ----------------
#define TOKENS_TOTAL (32*2048)
#define IN_DIM   128
#define HID      64
#define OUT_DIM  64
#define CODEBOOK 2048

#define TB       128
#define NTHREADS 256
#define NBLOCKS  (TOKENS_TOTAL/TB)     // 512
#define XT_STRIDE 130
#define CCH      64                     // codes per staged chunk
#define NCH      (CODEBOOK/CCH)         // 32

// output layout: msg ++ idx(as float) ++ loss
#define MSG_ELEMS ((size_t)TOKENS_TOTAL*OUT_DIM)
#define IDX_OFF   MSG_ELEMS
#define LOSS_OFF  (MSG_ELEMS + TOKENS_TOTAL)

// ---------------- smem layout (float/word offsets; 1 word = 4B) ----------------
#define OFF_E2   0                      // 2048 f
#define OFF_XT   2048                   // 64 x 130 f = 8320 -> end 10368
#define OFF_B    10368                  // B: 2 bufs x (h 64x36 + l 64x36) uint32 = 9216 w
#define B_ROW_W   36                    // uint32 per code row (32 data + 4 pad)
#define B_TILE_W  (64*B_ROW_W)          // 2304
#define B_BUF_W   (2*B_TILE_W)          // 4608 (h tile then l tile)
// MLP-phase overlays (dead regions during MLP)
#define OFF_W    10368                  // weights (<= 8192 f)
#define OFF_OBS  18560                  // obs tile / h2 (8192 f) -> end 26752
#define OFF_H1   2048                   // h1 (8192 f) overlays XT (written later)
#define SMEM_FLOATS 26752               // 107008 B

__device__ float g_e2[CODEBOOK];
__device__ float g_partial[NBLOCKS];

// ---------------- fp16 split helpers ----------------
__device__ __forceinline__ void split_h2(float x0, float x1, uint32_t& h, uint32_t& l) {
    __half h0 = __float2half_rn(x0);
    __half h1 = __float2half_rn(x1);
    float  l0 = x0 - __half2float(h0);
    float  l1 = x1 - __half2float(h1);
    __half2 hh = __halves2half2(h0, h1);
    __half2 ll = __floats2half2_rn(l0, l1);
    h = *(uint32_t*)&hh;
    l = *(uint32_t*)&ll;
}

__device__ __forceinline__ void mma16(float* c, const uint32_t* a, uint32_t b0, uint32_t b1) {
    asm volatile(
        "mma.sync.aligned.m16n8k16.row.col.f32.f16.f16.f32 "
        "{%0,%1,%2,%3}, {%4,%5,%6,%7}, {%8,%9}, {%0,%1,%2,%3};"
        : "+f"(c[0]), "+f"(c[1]), "+f"(c[2]), "+f"(c[3])
        : "r"(a[0]), "r"(a[1]), "r"(a[2]), "r"(a[3]), "r"(b0), "r"(b1));
}

// ---------------- packed fp32x2 helpers (MLP) ----------------
__device__ __forceinline__ unsigned long long dup2(float x) {
    unsigned long long r; asm("mov.b64 %0, {%1, %1};" : "=l"(r) : "f"(x)); return r;
}
__device__ __forceinline__ void ffma2(unsigned long long& d, unsigned long long a, unsigned long long b) {
    asm("fma.rn.f32x2 %0, %1, %2, %0;" : "+l"(d) : "l"(a), "l"(b));
}
__device__ __forceinline__ float lo32(unsigned long long v) { return __uint_as_float((unsigned)v); }
__device__ __forceinline__ float hi32(unsigned long long v) { return __uint_as_float((unsigned)(v >> 32)); }

// ---------------- MLP layer (proven rounds 1/3) ----------------
template<int KD, int NT, int OUTMODE, bool RELU>
__device__ __forceinline__ void mlp_layer(const float* in_s, int in_stride,
                                          const float* w_s, const float* __restrict__ b_g,
                                          float* out_s, int tid)
{
    const int jg = tid & 7;
    const int tg = tid >> 3;
    float bj[4][2];
#pragma unroll
    for (int jj = 0; jj < 4; jj++) {
        int j0 = jg*2 + 16*jj;
        bj[jj][0] = __ldg(b_g + j0);
        bj[jj][1] = __ldg(b_g + j0 + 1);
    }
    unsigned long long acc[NT][4];
#pragma unroll
    for (int it = 0; it < NT; it++)
#pragma unroll
        for (int jj = 0; jj < 4; jj++) acc[it][jj] = 0ULL;

#pragma unroll 4
    for (int k0 = 0; k0 < KD; k0 += 4) {
        float xin[NT][4];
#pragma unroll
        for (int it = 0; it < NT; it++) {
            float4 v = *(const float4*)(in_s + (tg*NT + it)*in_stride + k0);
            xin[it][0] = v.x; xin[it][1] = v.y; xin[it][2] = v.z; xin[it][3] = v.w;
        }
#pragma unroll
        for (int kk = 0; kk < 4; kk++) {
            unsigned long long wp[4];
#pragma unroll
            for (int jj = 0; jj < 4; jj++)
                wp[jj] = *(const unsigned long long*)(w_s + (k0+kk)*64 + jg*2 + 16*jj);
#pragma unroll
            for (int it = 0; it < NT; it++) {
                unsigned long long xd = dup2(xin[it][kk]);
#pragma unroll
                for (int jj = 0; jj < 4; jj++) ffma2(acc[it][jj], xd, wp[jj]);
            }
        }
    }
#pragma unroll
    for (int it = 0; it < NT; it++) {
        int t = tg*NT + it;
#pragma unroll
        for (int jj = 0; jj < 4; jj++) {
            int j0 = jg*2 + 16*jj;
            float v0 = lo32(acc[it][jj]) + bj[jj][0];
            float v1 = hi32(acc[it][jj]) + bj[jj][1];
            if (RELU) { v0 = fmaxf(v0, 0.0f); v1 = fmaxf(v1, 0.0f); }
            if (OUTMODE == 0) {
                out_s[t*64 + j0]     = v0;
                out_s[t*64 + j0 + 1] = v1;
            } else {
                out_s[j0*XT_STRIDE + t]       = v0;
                out_s[(j0 + 1)*XT_STRIDE + t] = v1;
            }
        }
    }
}

// ---------------- |e|^2 precompute (8 threads per code) ----------------
__global__ void e2_kernel(const float* __restrict__ cb) {
    int gt  = blockIdx.x * 256 + threadIdx.x;
    int c   = gt >> 3;
    int sub = gt & 7;
    const float4* p = (const float4*)(cb + (size_t)c * OUT_DIM + sub*8);
    float4 a = p[0], b = p[1];
    float s = a.x*a.x + a.y*a.y + a.z*a.z + a.w*a.w
            + b.x*b.x + b.y*b.y + b.z*b.z + b.w*b.w;
    s += __shfl_xor_sync(0xffffffffu, s, 1);
    s += __shfl_xor_sync(0xffffffffu, s, 2);
    s += __shfl_xor_sync(0xffffffffu, s, 4);
    if (sub == 0) g_e2[c] = s;
}

// ---------------- codebook chunk staging ----------------
__device__ __forceinline__ void b_ldg(const float* __restrict__ cb, int ch, int tid, float4* v) {
    int c = tid >> 2, qg = tid & 3;   // code 0..63, k-quarter 0..3
    const float4* p = (const float4*)(cb + (size_t)(ch*CCH + c)*OUT_DIM + qg*16);
#pragma unroll
    for (int i = 0; i < 4; i++) v[i] = p[i];
}
__device__ __forceinline__ void b_sts(uint32_t* bbuf, int tid, const float4* v) {
    int c = tid >> 2, qg = tid & 3;
    uint32_t hw[8], lw[8];
#pragma unroll
    for (int i = 0; i < 4; i++) {
        split_h2(v[i].x, v[i].y, hw[i*2],   lw[i*2]);
        split_h2(v[i].z, v[i].w, hw[i*2+1], lw[i*2+1]);
    }
    uint32_t* hrow = bbuf + c*B_ROW_W + qg*8;
    uint32_t* lrow = hrow + B_TILE_W;
    *(uint4*)(hrow)     = make_uint4(hw[0], hw[1], hw[2], hw[3]);
    *(uint4*)(hrow + 4) = make_uint4(hw[4], hw[5], hw[6], hw[7]);
    *(uint4*)(lrow)     = make_uint4(lw[0], lw[1], lw[2], lw[3]);
    *(uint4*)(lrow + 4) = make_uint4(lw[4], lw[5], lw[6], lw[7]);
}

// ---------------- fused kernel ----------------
__global__ void __launch_bounds__(NTHREADS, 1)
vq_main(const float* __restrict__ obs,
        const float* __restrict__ W1, const float* __restrict__ b1,
        const float* __restrict__ W2, const float* __restrict__ b2,
        const float* __restrict__ W3, const float* __restrict__ b3,
        const float* __restrict__ cb,
        float* __restrict__ out)
{
    extern __shared__ float sm[];
    const int tid  = threadIdx.x;
    const int wid  = tid >> 5;
    const int lane = tid & 31;
    const int r    = lane >> 2;      // 0..7
    const int q    = lane & 3;       // 0..3
    const int tok0 = blockIdx.x * TB;

    // e2 table -> smem (region unused by MLP)
    for (int i = tid; i < CODEBOOK; i += NTHREADS) sm[OFF_E2 + i] = g_e2[i];

    // ================= MLP (FFMA2) =================
    {
        const float4* w4 = (const float4*)W1;
        float4* d4 = (float4*)(sm + OFF_W);
        for (int i = tid; i < (IN_DIM*HID)/4; i += NTHREADS) d4[i] = w4[i];
    }
    for (int half = 0; half < 2; half++) {
        __syncthreads();
        const float4* o4 = (const float4*)(obs + (size_t)(tok0 + half*64) * IN_DIM);
        float4* d4 = (float4*)(sm + OFF_OBS);
        for (int i = tid; i < (64*IN_DIM)/4; i += NTHREADS) d4[i] = o4[i];
        __syncthreads();
        mlp_layer<IN_DIM, 2, 0, true>(sm + OFF_OBS, IN_DIM, sm + OFF_W, b1,
                                      sm + OFF_H1 + half*64*HID, tid);
    }
    __syncthreads();
    {
        const float4* w4 = (const float4*)W2;
        float4* d4 = (float4*)(sm + OFF_W);
        for (int i = tid; i < (HID*HID)/4; i += NTHREADS) d4[i] = w4[i];
    }
    __syncthreads();
    mlp_layer<HID, 4, 0, true>(sm + OFF_H1, HID, sm + OFF_W, b2, sm + OFF_OBS, tid);
    __syncthreads();
    {
        const float4* w4 = (const float4*)W3;
        float4* d4 = (float4*)(sm + OFF_W);
        for (int i = tid; i < (HID*OUT_DIM)/4; i += NTHREADS) d4[i] = w4[i];
    }
    __syncthreads();
    // x -> XT [64 k][130 tokens], exact fp32
    mlp_layer<HID, 4, 1, false>(sm + OFF_OBS, HID, sm + OFF_W, b3, sm + OFF_XT, tid);
    __syncthreads();

    // ========== A fragments (m16 x k64, fp16 hi/lo), built once per warp ==========
    // m16n8k16 A layout: a0=(r,2q|2q+1) a1=(r+8,..) a2=(r,2q+8|+9) a3=(r+8,+8|+9)
    const float* xsT = sm + OFF_XT;
    const int tokw = wid * 16;
    uint32_t Ah[4][4], Al[4][4];
#pragma unroll
    for (int kb = 0; kb < 4; kb++) {
        int k0 = kb*16;
        const float* x0 = xsT + tokw;
        float v00 = x0[(k0 + 2*q    )*XT_STRIDE + r];
        float v01 = x0[(k0 + 2*q + 1)*XT_STRIDE + r];
        float v10 = x0[(k0 + 2*q    )*XT_STRIDE + r + 8];
        float v11 = x0[(k0 + 2*q + 1)*XT_STRIDE + r + 8];
        float v20 = x0[(k0 + 2*q + 8)*XT_STRIDE + r];
        float v21 = x0[(k0 + 2*q + 9)*XT_STRIDE + r];
        float v30 = x0[(k0 + 2*q + 8)*XT_STRIDE + r + 8];
        float v31 = x0[(k0 + 2*q + 9)*XT_STRIDE + r + 8];
        split_h2(v00, v01, Ah[kb][0], Al[kb][0]);
        split_h2(v10, v11, Ah[kb][1], Al[kb][1]);
        split_h2(v20, v21, Ah[kb][2], Al[kb][2]);
        split_h2(v30, v31, Ah[kb][3], Al[kb][3]);
    }

    // ================= VQ: mma.sync fp16 m16n8k16, 3-term split =================
    float best_d0 = FLT_MAX, best_d1 = FLT_MAX;
    int   best_c0 = 0,       best_c1 = 0;

    uint32_t* bw = (uint32_t*)(sm + OFF_B);

    // prologue: stage chunk 0 into buf 0
    {
        float4 st[4];
        b_ldg(cb, 0, tid, st);
        b_sts(bw, tid, st);
        __syncthreads();
    }

    for (int ch = 0; ch < NCH; ch++) {
        const int buf = ch & 1;
        float4 st[4];
        const bool more = (ch + 1 < NCH);
        if (more) b_ldg(cb, ch + 1, tid, st);   // prefetch next chunk

        const uint32_t* bh = bw + buf*B_BUF_W;
        const uint32_t* bl = bh + B_TILE_W;

#pragma unroll
        for (int grp = 0; grp < 2; grp++) {
            float accM[4][4], accC1[4][4], accC2[4][4];
#pragma unroll
            for (int g = 0; g < 4; g++)
#pragma unroll
                for (int j = 0; j < 4; j++) { accM[g][j]=0.f; accC1[g][j]=0.f; accC2[g][j]=0.f; }

            // B col (code) = groupID = r; code_local = grp*32 + g*8 + r
            int rb0 = (grp*32 +  0 + r)*B_ROW_W + q;
            int rb1 = (grp*32 +  8 + r)*B_ROW_W + q;
            int rb2 = (grp*32 + 16 + r)*B_ROW_W + q;
            int rb3 = (grp*32 + 24 + r)*B_ROW_W + q;

#pragma unroll
            for (int kb = 0; kb < 4; kb++) {
                int ko = kb*8;
                uint32_t bh0[4], bh1[4], bl0[4], bl1[4];
                bh0[0] = bh[rb0 + ko]; bh1[0] = bh[rb0 + ko + 4];
                bh0[1] = bh[rb1 + ko]; bh1[1] = bh[rb1 + ko + 4];
                bh0[2] = bh[rb2 + ko]; bh1[2] = bh[rb2 + ko + 4];
                bh0[3] = bh[rb3 + ko]; bh1[3] = bh[rb3 + ko + 4];
                bl0[0] = bl[rb0 + ko]; bl1[0] = bl[rb0 + ko + 4];
                bl0[1] = bl[rb1 + ko]; bl1[1] = bl[rb1 + ko + 4];
                bl0[2] = bl[rb2 + ko]; bl1[2] = bl[rb2 + ko + 4];
                bl0[3] = bl[rb3 + ko]; bl1[3] = bl[rb3 + ko + 4];
#pragma unroll
                for (int g = 0; g < 4; g++) mma16(accM[g],  Ah[kb], bh0[g], bh1[g]);
#pragma unroll
                for (int g = 0; g < 4; g++) mma16(accC1[g], Ah[kb], bl0[g], bl1[g]);
#pragma unroll
                for (int g = 0; g < 4; g++) mma16(accC2[g], Al[kb], bh0[g], bh1[g]);
            }

            // epilogue: dist = e2 - 2*s, running argmin (codes ascending per slot)
#pragma unroll
            for (int g = 0; g < 4; g++) {
                int code0 = ch*CCH + grp*32 + g*8 + 2*q;
                float e20 = sm[OFF_E2 + code0];
                float e21 = sm[OFF_E2 + code0 + 1];
                float s0 = accM[g][0] + accC1[g][0] + accC2[g][0];
                float s1 = accM[g][1] + accC1[g][1] + accC2[g][1];
                float s2 = accM[g][2] + accC1[g][2] + accC2[g][2];
                float s3 = accM[g][3] + accC1[g][3] + accC2[g][3];
                float d0 = fmaf(-2.0f, s0, e20);
                float d1 = fmaf(-2.0f, s1, e21);
                float d2 = fmaf(-2.0f, s2, e20);
                float d3 = fmaf(-2.0f, s3, e21);
                if (d0 < best_d0) { best_d0 = d0; best_c0 = code0; }
                if (d1 < best_d0) { best_d0 = d1; best_c0 = code0 + 1; }
                if (d2 < best_d1) { best_d1 = d2; best_c1 = code0; }
                if (d3 < best_d1) { best_d1 = d3; best_c1 = code0 + 1; }
            }
        }

        __syncthreads();                 // all warps done reading this buf
        if (more) b_sts(bw + (1 - buf)*B_BUF_W, tid, st);
        __syncthreads();                 // staged data visible
    }

    // ---- cross-lane argmin (4 lanes per token row), tie-break: smaller code ----
#pragma unroll
    for (int m = 1; m <= 2; m <<= 1) {
        float od0 = __shfl_xor_sync(0xffffffffu, best_d0, m);
        int   oc0 = __shfl_xor_sync(0xffffffffu, best_c0, m);
        float od1 = __shfl_xor_sync(0xffffffffu, best_d1, m);
        int   oc1 = __shfl_xor_sync(0xffffffffu, best_c1, m);
        if (od0 < best_d0 || (od0 == best_d0 && oc0 < best_c0)) { best_d0 = od0; best_c0 = oc0; }
        if (od1 < best_d1 || (od1 == best_d1 && oc1 < best_c1)) { best_d1 = od1; best_c1 = oc1; }
    }

    int* sIdx = (int*)(sm + OFF_B);      // B region dead now
    if (q == 0) {
        int t0 = tokw + r;
        sIdx[t0]     = best_c0;
        sIdx[t0 + 8] = best_c1;
        out[IDX_OFF + (size_t)(tok0 + t0)]     = (float)best_c0;
        out[IDX_OFF + (size_t)(tok0 + t0 + 8)] = (float)best_c1;
    }
    __syncthreads();

    // ---- msg write + commitment-loss partial (exact fp32 x) ----
    float part = 0.0f;
    for (int f = tid; f < TB*OUT_DIM; f += NTHREADS) {
        int t = f >> 6, j = f & 63;
        int c = sIdx[t];
        float qv = __ldg(cb + (size_t)c * OUT_DIM + j);
        float xv = xsT[j*XT_STRIDE + t];
        out[(size_t)(tok0 + t)*OUT_DIM + j] = xv + (qv - xv);
        float dd = qv - xv;
        part += dd * dd;
    }
#pragma unroll
    for (int o = 16; o > 0; o >>= 1)
        part += __shfl_down_sync(0xffffffffu, part, o);
    __shared__ float swred[8];
    if ((tid & 31) == 0) swred[tid >> 5] = part;
    __syncthreads();
    if (tid == 0) {
        float s = 0.0f;
#pragma unroll
        for (int w = 0; w < 8; w++) s += swred[w];
        g_partial[blockIdx.x] = s;
    }
}

// ---------------- deterministic loss reduction ----------------
__global__ void loss_reduce(float* __restrict__ out) {
    __shared__ float s[NBLOCKS];
    int t = threadIdx.x;
    s[t] = g_partial[t];
    __syncthreads();
    for (int o = NBLOCKS/2; o > 0; o >>= 1) {
        if (t < o) s[t] += s[t + o];
        __syncthreads();
    }
    if (t == 0) out[LOSS_OFF] = s[0] * (1.0f / (float)MSG_ELEMS);
}

extern "C" void kernel_launch(void* const* d_in, const int* in_sizes, int n_in,
                              void* d_out, int out_size)
{
    const float* obs = (const float*)d_in[0];
    const float* W1  = (const float*)d_in[1];
    const float* b1  = (const float*)d_in[2];
    const float* W2  = (const float*)d_in[3];
    const float* b2  = (const float*)d_in[4];
    const float* W3  = (const float*)d_in[5];
    const float* b3  = (const float*)d_in[6];
    const float* cb  = (const float*)d_in[7];
    float* out = (float*)d_out;

    cudaFuncSetAttribute(vq_main, cudaFuncAttributeMaxDynamicSharedMemorySize,
                         SMEM_FLOATS * (int)sizeof(float));

    e2_kernel<<<CODEBOOK*8/256, 256>>>(cb);
    vq_main<<<NBLOCKS, NTHREADS, SMEM_FLOATS * sizeof(float)>>>(
        obs, W1, b1, W2, b2, W3, b3, cb, out);
    loss_reduce<<<1, NBLOCKS>>>(out);
}